// round 2
// baseline (speedup 1.0000x reference)
#include <cuda_runtime.h>
#include <math.h>

// Problem dims (fixed by the dataset)
#define BB   4096      // batch
#define DD   1024      // input dim
#define RB   2048      // reservoir dim
#define MAXD 2560      // padded output width
#define GN   (3*RB)    // gate GEMM N = 6144

// Scratch (device-global: no allocation allowed in kernel_launch)
__device__ float g_Z[(size_t)BB * RB];        // input_part + reservoir_part
__device__ float g_G[(size_t)BB * GN];        // sigmoid(X @ W_gate^T)

// ---------------------------------------------------------------------------
// Generic NT GEMM phase: acc += A[bm:bm+128, k] * W[bn:bn+128, k]^T over K.
// A row-major (lda), W row-major (ldb), both K-contiguous. BK=16.
// Thread layout: 256 threads = 16x16; thread (tx,ty) owns 8x8 microtile.
// ---------------------------------------------------------------------------
__device__ __forceinline__ void gemm_phase(
    const float* __restrict__ A, int lda,
    const float* __restrict__ W, int ldb,
    int K, int bm, int bn, int tid, int tx, int ty,
    float (&acc)[8][8], float (*As)[128], float (*Bs)[128])
{
    for (int k0 = 0; k0 < K; k0 += 16) {
        // Load 128x16 A tile and 128x16 W tile, transposed into smem [k][m]
        #pragma unroll
        for (int i = 0; i < 2; ++i) {
            int f   = tid + i * 256;       // 0..511
            int row = f >> 2;              // 0..127
            int c4  = (f & 3) * 4;         // 0,4,8,12
            float4 va = *(const float4*)(A + (size_t)(bm + row) * lda + k0 + c4);
            As[c4 + 0][row] = va.x;
            As[c4 + 1][row] = va.y;
            As[c4 + 2][row] = va.z;
            As[c4 + 3][row] = va.w;
            float4 vb = *(const float4*)(W + (size_t)(bn + row) * ldb + k0 + c4);
            Bs[c4 + 0][row] = vb.x;
            Bs[c4 + 1][row] = vb.y;
            Bs[c4 + 2][row] = vb.z;
            Bs[c4 + 3][row] = vb.w;
        }
        __syncthreads();

        #pragma unroll
        for (int k = 0; k < 16; ++k) {
            float a[8], b[8];
            *(float4*)&a[0] = *(const float4*)&As[k][ty * 8];
            *(float4*)&a[4] = *(const float4*)&As[k][ty * 8 + 4];
            *(float4*)&b[0] = *(const float4*)&Bs[k][tx * 8];
            *(float4*)&b[4] = *(const float4*)&Bs[k][tx * 8 + 4];
            #pragma unroll
            for (int i = 0; i < 8; ++i)
                #pragma unroll
                for (int j = 0; j < 8; ++j)
                    acc[i][j] = fmaf(a[i], b[j], acc[i][j]);
        }
        __syncthreads();
    }
}

// ---------------------------------------------------------------------------
// Kernel 1: Z = X @ W_in^T + P @ W_res^T   (4096 x 2048)
// ---------------------------------------------------------------------------
__global__ __launch_bounds__(256, 2) void gemm_z_kernel(
    const float* __restrict__ X,     // [4096,1024]
    const float* __restrict__ P,     // [4096,2560] (first 2048 cols valid)
    const float* __restrict__ Win,   // [2048,1024]
    const float* __restrict__ Wres)  // [2048,2048]
{
    __shared__ float As[16][128];
    __shared__ float Bs[16][128];
    float acc[8][8];
    #pragma unroll
    for (int i = 0; i < 8; ++i)
        #pragma unroll
        for (int j = 0; j < 8; ++j) acc[i][j] = 0.0f;

    int tid = threadIdx.x;
    int tx  = tid & 15;
    int ty  = tid >> 4;
    int bm  = blockIdx.y * 128;
    int bn  = blockIdx.x * 128;

    gemm_phase(X, DD,   Win,  DD, DD, bm, bn, tid, tx, ty, acc, As, Bs);
    gemm_phase(P, MAXD, Wres, RB, RB, bm, bn, tid, tx, ty, acc, As, Bs);

    #pragma unroll
    for (int i = 0; i < 8; ++i) {
        float4 v0 = make_float4(acc[i][0], acc[i][1], acc[i][2], acc[i][3]);
        float4 v1 = make_float4(acc[i][4], acc[i][5], acc[i][6], acc[i][7]);
        size_t base = (size_t)(bm + ty * 8 + i) * RB + bn + tx * 8;
        *(float4*)(g_Z + base)     = v0;
        *(float4*)(g_Z + base + 4) = v1;
    }
}

// ---------------------------------------------------------------------------
// Kernel 2: G = sigmoid(X @ W_gate^T)   (4096 x 6144)
// ---------------------------------------------------------------------------
__global__ __launch_bounds__(256, 2) void gemm_g_kernel(
    const float* __restrict__ X,     // [4096,1024]
    const float* __restrict__ Wg)    // [6144,1024]
{
    __shared__ float As[16][128];
    __shared__ float Bs[16][128];
    float acc[8][8];
    #pragma unroll
    for (int i = 0; i < 8; ++i)
        #pragma unroll
        for (int j = 0; j < 8; ++j) acc[i][j] = 0.0f;

    int tid = threadIdx.x;
    int tx  = tid & 15;
    int ty  = tid >> 4;
    int bm  = blockIdx.y * 128;
    int bn  = blockIdx.x * 128;

    gemm_phase(X, DD, Wg, DD, DD, bm, bn, tid, tx, ty, acc, As, Bs);

    #pragma unroll
    for (int i = 0; i < 8; ++i) {
        #pragma unroll
        for (int j = 0; j < 8; ++j)
            acc[i][j] = 1.0f / (1.0f + expf(-acc[i][j]));   // sigmoid
        float4 v0 = make_float4(acc[i][0], acc[i][1], acc[i][2], acc[i][3]);
        float4 v1 = make_float4(acc[i][4], acc[i][5], acc[i][6], acc[i][7]);
        size_t base = (size_t)(bm + ty * 8 + i) * GN + bn + tx * 8;
        *(float4*)(g_G + base)     = v0;
        *(float4*)(g_G + base + 4) = v1;
    }
}

// ---------------------------------------------------------------------------
// Kernel 3: combine + spike + pad.
// out[b, c] for c < 2048:
//   s = 0.9*f*prev + 0.1*tanh(i*z);  s = o*s;  if (s > 0.5) s -= 0.5
// out[b, 2048:2560] = 0
// One thread per float4 over 4096 x 640 float4s.
// ---------------------------------------------------------------------------
__global__ void combine_kernel(const float* __restrict__ P, float* __restrict__ out)
{
    size_t idx = (size_t)blockIdx.x * blockDim.x + threadIdx.x;
    if (idx >= (size_t)BB * (MAXD / 4)) return;
    int row = (int)(idx / (MAXD / 4));
    int c4  = (int)(idx % (MAXD / 4));

    float4 o4;
    if (c4 < RB / 4) {
        int c = c4 * 4;
        float4 z  = *(const float4*)(g_Z + (size_t)row * RB + c);
        float4 gi = *(const float4*)(g_G + (size_t)row * GN + c);
        float4 gf = *(const float4*)(g_G + (size_t)row * GN + RB + c);
        float4 go = *(const float4*)(g_G + (size_t)row * GN + 2 * RB + c);
        float4 p  = *(const float4*)(P   + (size_t)row * MAXD + c);

        float zz[4] = {z.x, z.y, z.z, z.w};
        float ii[4] = {gi.x, gi.y, gi.z, gi.w};
        float ff[4] = {gf.x, gf.y, gf.z, gf.w};
        float oo[4] = {go.x, go.y, go.z, go.w};
        float pp[4] = {p.x, p.y, p.z, p.w};
        float s[4];
        #pragma unroll
        for (int l = 0; l < 4; ++l) {
            float v = 0.9f * (ff[l] * pp[l]) + 0.1f * tanhf(ii[l] * zz[l]);
            v = oo[l] * v;
            if (v > 0.5f) v -= 0.5f;
            s[l] = v;
        }
        o4 = make_float4(s[0], s[1], s[2], s[3]);
    } else {
        o4 = make_float4(0.0f, 0.0f, 0.0f, 0.0f);
    }
    *(float4*)(out + (size_t)row * MAXD + c4 * 4) = o4;
}

// ---------------------------------------------------------------------------
extern "C" void kernel_launch(void* const* d_in, const int* in_sizes, int n_in,
                              void* d_out, int out_size)
{
    const float* X    = (const float*)d_in[0];  // inputs     [4096,1024]
    const float* P    = (const float*)d_in[1];  // prev_state [4096,2560]
    const float* Win  = (const float*)d_in[2];  // W_in       [2048,1024]
    const float* Wres = (const float*)d_in[3];  // W_res      [2048,2048]
    const float* Wg   = (const float*)d_in[4];  // W_gate     [6144,1024]
    float* out = (float*)d_out;                 // [4096,2560]

    gemm_z_kernel<<<dim3(RB / 128, BB / 128), 256>>>(X, P, Win, Wres);
    gemm_g_kernel<<<dim3(GN / 128, BB / 128), 256>>>(X, Wg);
    combine_kernel<<<(BB * (MAXD / 4) + 255) / 256, 256>>>(P, out);
}

// round 9
// speedup vs baseline: 1.9110x; 1.9110x over previous
#include <cuda_runtime.h>
#include <cuda_bf16.h>
#include <cstdint>
#include <math.h>

// ---------------------------------------------------------------------------
// Problem dims
#define BB   4096
#define DD   1024
#define RB   2048
#define GN   (3*RB)     // 6144
#define MAXD 2560

// ---------------------------------------------------------------------------
// Device-global scratch (bf16 3-way splits + fp32 intermediates)
__device__ __nv_bfloat16 g_X0[(size_t)BB*DD], g_X1[(size_t)BB*DD], g_X2[(size_t)BB*DD];
__device__ __nv_bfloat16 g_P0[(size_t)BB*RB], g_P1[(size_t)BB*RB], g_P2[(size_t)BB*RB];
__device__ __nv_bfloat16 g_Wi0[(size_t)RB*DD], g_Wi1[(size_t)RB*DD], g_Wi2[(size_t)RB*DD];
__device__ __nv_bfloat16 g_Wr0[(size_t)RB*RB], g_Wr1[(size_t)RB*RB], g_Wr2[(size_t)RB*RB];
__device__ __nv_bfloat16 g_Wg0[(size_t)GN*DD], g_Wg1[(size_t)GN*DD], g_Wg2[(size_t)GN*DD];
__device__ float g_Z[(size_t)BB*RB];
__device__ float g_G[(size_t)BB*GN];

// ---------------------------------------------------------------------------
// Tiling constants
#define BK          64
#define TILE_BYTES  (128 * 128)            // 128 rows x 64 bf16 cols = 16384 B
#define STAGE_BYTES (6 * TILE_BYTES)       // A0,A1,A2,B0,B1,B2 = 98304 B
#define SMEM_SIZE   (2 * STAGE_BYTES)      // 196608 B

__device__ __forceinline__ uint32_t smem_to_u32(const void* p) {
    uint32_t a;
    asm("{ .reg .u64 t; cvta.to.shared.u64 t, %1; cvt.u32.u64 %0, t; }" : "=r"(a) : "l"(p));
    return a;
}

__device__ __forceinline__ void ldsm_x4(uint32_t (&r)[4], uint32_t addr) {
    asm volatile("ldmatrix.sync.aligned.m8n8.x4.shared.b16 {%0,%1,%2,%3}, [%4];"
                 : "=r"(r[0]), "=r"(r[1]), "=r"(r[2]), "=r"(r[3]) : "r"(addr));
}

__device__ __forceinline__ void mma_bf16(float (&c)[4], const uint32_t (&a)[4],
                                         const uint32_t* b) {
    asm volatile("mma.sync.aligned.m16n8k16.row.col.f32.bf16.bf16.f32 "
                 "{%0,%1,%2,%3}, {%4,%5,%6,%7}, {%8,%9}, {%0,%1,%2,%3};"
                 : "+f"(c[0]), "+f"(c[1]), "+f"(c[2]), "+f"(c[3])
                 : "r"(a[0]), "r"(a[1]), "r"(a[2]), "r"(a[3]), "r"(b[0]), "r"(b[1]));
}

// cp.async one 128x64 bf16 tile (gmem row stride ld elems) into SW128 smem tile.
__device__ __forceinline__ void cp_tile(uint32_t sm_tile, const __nv_bfloat16* __restrict__ g,
                                        int ld, int tid) {
    #pragma unroll
    for (int i = 0; i < 4; ++i) {
        int c   = tid + (i << 8);          // 0..1023 16B-chunks
        int row = c >> 3;                  // 0..127
        int ch  = c & 7;                   // 0..7
        uint32_t off = (uint32_t)((row << 7) | (((ch ^ (row & 7))) << 4));
        const void* gp = g + (size_t)row * ld + (ch << 3);
        asm volatile("cp.async.cg.shared.global [%0], [%1], 16;"
                     :: "r"(sm_tile + off), "l"(gp));
    }
}
#define CP_COMMIT()  asm volatile("cp.async.commit_group;" ::: "memory")
#define CP_WAIT(n)   asm volatile("cp.async.wait_group %0;" :: "n"(n) : "memory")

// ---------------------------------------------------------------------------
// Load the 4 ldmatrix.x4 A fragments for one bf16-split tile at k16-step ks.
__device__ __forceinline__ void load_afr(uint32_t sTile, int lane, int wm, int ks,
                                         uint32_t (&afr)[4][4]) {
    int r  = wm + (((lane >> 3) & 1) << 3) + (lane & 7);
    int kc = (ks << 1) + (lane >> 4);
    #pragma unroll
    for (int mi = 0; mi < 4; ++mi) {
        int rr = r + mi * 16;
        uint32_t addr = (uint32_t)((rr << 7) | (((kc ^ (rr & 7))) << 4));
        ldsm_x4(afr[mi], sTile + addr);
    }
}

// 16 MMAs of one product into one accumulator set.
__device__ __forceinline__ void do_product(float (&acc)[4][4][4],
                                           const uint32_t (&afr)[4][4],
                                           const uint32_t (&bfr)[2][4]) {
    #pragma unroll
    for (int mi = 0; mi < 4; ++mi)
        #pragma unroll
        for (int nj = 0; nj < 4; ++nj)
            mma_bf16(acc[mi][nj], afr[mi], &bfr[nj >> 1][(nj & 1) << 1]);
}

// ---------------------------------------------------------------------------
// Compute one BK=64 window: 6 split-products, magnitude-ordered accumulation.
//   accL <- a0*b0 only (dominant term; one fp32 round per k16, like plain GEMM)
//   accS <- a1*b0, a0*b1, a1*b1, a2*b0, a0*b2 (max ~2^-9; separate accumulator
//           so their rounding never happens at ulp(large sum))
__device__ __forceinline__ void compute_stage(uint32_t sA, uint32_t sB,
                                              int lane, int wm, int wn,
                                              float (&accL)[4][4][4],
                                              float (&accS)[4][4][4])
{
    #pragma unroll
    for (int ks = 0; ks < 4; ++ks) {
        // B fragments for all 3 splits
        uint32_t bfr[3][2][4];
        {
            int r  = wn + (((lane >> 4) & 1) << 3) + (lane & 7);
            int kc = (ks << 1) + ((lane >> 3) & 1);
            #pragma unroll
            for (int nj2 = 0; nj2 < 2; ++nj2) {
                int rr = r + nj2 * 16;
                uint32_t addr = (uint32_t)((rr << 7) | (((kc ^ (rr & 7))) << 4));
                #pragma unroll
                for (int s = 0; s < 3; ++s)
                    ldsm_x4(bfr[s][nj2], sB + s * TILE_BYTES + addr);
            }
        }
        // A split 0: products (0,0)->L, (0,1)->S, (0,2)->S
        {
            uint32_t afr[4][4];
            load_afr(sA + 0 * TILE_BYTES, lane, wm, ks, afr);
            do_product(accL, afr, bfr[0]);
            do_product(accS, afr, bfr[1]);
            do_product(accS, afr, bfr[2]);
        }
        // A split 1: products (1,0)->S, (1,1)->S
        {
            uint32_t afr[4][4];
            load_afr(sA + 1 * TILE_BYTES, lane, wm, ks, afr);
            do_product(accS, afr, bfr[0]);
            do_product(accS, afr, bfr[1]);
        }
        // A split 2: product (2,0)->S
        {
            uint32_t afr[4][4];
            load_afr(sA + 2 * TILE_BYTES, lane, wm, ks, afr);
            do_product(accS, afr, bfr[0]);
        }
    }
}

// One K-phase: accumulate A[bm:,k]*B[bn:,k]^T for nwin BK-windows (double buffered).
__device__ __forceinline__ void run_phase(
    const __nv_bfloat16* __restrict__ A0, const __nv_bfloat16* __restrict__ A1,
    const __nv_bfloat16* __restrict__ A2, int lda,
    const __nv_bfloat16* __restrict__ B0, const __nv_bfloat16* __restrict__ B1,
    const __nv_bfloat16* __restrict__ B2, int ldb,
    int nwin, uint32_t sb, int tid, int lane, int wm, int wn,
    float (&accL)[4][4][4], float (&accS)[4][4][4])
{
    // prologue: window 0 -> stage 0
    cp_tile(sb + 0 * TILE_BYTES, A0, lda, tid);
    cp_tile(sb + 1 * TILE_BYTES, A1, lda, tid);
    cp_tile(sb + 2 * TILE_BYTES, A2, lda, tid);
    cp_tile(sb + 3 * TILE_BYTES, B0, ldb, tid);
    cp_tile(sb + 4 * TILE_BYTES, B1, ldb, tid);
    cp_tile(sb + 5 * TILE_BYTES, B2, ldb, tid);
    CP_COMMIT();

    for (int w = 0; w < nwin; ++w) {
        if (w + 1 < nwin) {
            uint32_t st = sb + ((w + 1) & 1) * STAGE_BYTES;
            size_t koff = (size_t)(w + 1) * BK;
            cp_tile(st + 0 * TILE_BYTES, A0 + koff, lda, tid);
            cp_tile(st + 1 * TILE_BYTES, A1 + koff, lda, tid);
            cp_tile(st + 2 * TILE_BYTES, A2 + koff, lda, tid);
            cp_tile(st + 3 * TILE_BYTES, B0 + koff, ldb, tid);
            cp_tile(st + 4 * TILE_BYTES, B1 + koff, ldb, tid);
            cp_tile(st + 5 * TILE_BYTES, B2 + koff, ldb, tid);
            CP_COMMIT();
            CP_WAIT(1);
        } else {
            CP_WAIT(0);
        }
        __syncthreads();
        uint32_t st = sb + (w & 1) * STAGE_BYTES;
        compute_stage(st, st + 3 * TILE_BYTES, lane, wm, wn, accL, accS);
        __syncthreads();
    }
}

// ---------------------------------------------------------------------------
// Fused GEMM kernel: blocks [0,512) -> Z (K=1024 then 2048), [512,2048) -> gates
__global__ __launch_bounds__(256, 1) void gemm_fused_kernel()
{
    extern __shared__ char smem[];
    uint32_t sb = smem_to_u32(smem);
    int tid  = threadIdx.x;
    int lane = tid & 31;
    int wid  = tid >> 5;
    int wm   = (wid & 1) * 64;     // warp M offset within 128
    int wn   = (wid >> 1) * 32;    // warp N offset within 128

    int bz = blockIdx.x;
    bool isZ = bz < 512;
    int bm, bn;
    if (isZ) { bm = (bz >> 4) * 128; bn = (bz & 15) * 128; }
    else     { int g = bz - 512; bm = (g / 48) * 128; bn = (g % 48) * 128; }

    float accL[4][4][4], accS[4][4][4];
    #pragma unroll
    for (int i = 0; i < 4; ++i)
        #pragma unroll
        for (int j = 0; j < 4; ++j)
            #pragma unroll
            for (int l = 0; l < 4; ++l) { accL[i][j][l] = 0.0f; accS[i][j][l] = 0.0f; }

    if (isZ) {
        run_phase(g_X0 + (size_t)bm * DD, g_X1 + (size_t)bm * DD, g_X2 + (size_t)bm * DD, DD,
                  g_Wi0 + (size_t)bn * DD, g_Wi1 + (size_t)bn * DD, g_Wi2 + (size_t)bn * DD, DD,
                  DD / BK, sb, tid, lane, wm, wn, accL, accS);
        run_phase(g_P0 + (size_t)bm * RB, g_P1 + (size_t)bm * RB, g_P2 + (size_t)bm * RB, RB,
                  g_Wr0 + (size_t)bn * RB, g_Wr1 + (size_t)bn * RB, g_Wr2 + (size_t)bn * RB, RB,
                  RB / BK, sb, tid, lane, wm, wn, accL, accS);
    } else {
        run_phase(g_X0 + (size_t)bm * DD, g_X1 + (size_t)bm * DD, g_X2 + (size_t)bm * DD, DD,
                  g_Wg0 + (size_t)bn * DD, g_Wg1 + (size_t)bn * DD, g_Wg2 + (size_t)bn * DD, DD,
                  DD / BK, sb, tid, lane, wm, wn, accL, accS);
    }

    // Epilogue: c-frag (mi,nj): c0,c1 at row t/4, cols (t%4)*2; c2,c3 at row t/4+8
    float* outp = isZ ? g_Z : g_G;
    int ldc = isZ ? RB : GN;
    int rbase = bm + wm + (lane >> 2);
    int cbase = bn + wn + ((lane & 3) << 1);
    #pragma unroll
    for (int mi = 0; mi < 4; ++mi) {
        #pragma unroll
        for (int nj = 0; nj < 4; ++nj) {
            int r0 = rbase + mi * 16;
            int c0 = cbase + nj * 8;
            float v0 = accL[mi][nj][0] + accS[mi][nj][0];
            float v1 = accL[mi][nj][1] + accS[mi][nj][1];
            float v2 = accL[mi][nj][2] + accS[mi][nj][2];
            float v3 = accL[mi][nj][3] + accS[mi][nj][3];
            if (!isZ) {
                v0 = 1.0f / (1.0f + expf(-v0));
                v1 = 1.0f / (1.0f + expf(-v1));
                v2 = 1.0f / (1.0f + expf(-v2));
                v3 = 1.0f / (1.0f + expf(-v3));
            }
            *reinterpret_cast<float2*>(outp + (size_t)r0 * ldc + c0)       = make_float2(v0, v1);
            *reinterpret_cast<float2*>(outp + (size_t)(r0 + 8) * ldc + c0) = make_float2(v2, v3);
        }
    }
}

// ---------------------------------------------------------------------------
// fp32 -> 3x bf16 split kernels (a = b0 + b1 + b2 to within 2^-27 relative)
__device__ __forceinline__ void split_store(const float4 v, __nv_bfloat16* d0,
                                            __nv_bfloat16* d1, __nv_bfloat16* d2, size_t o)
{
    float a[4] = {v.x, v.y, v.z, v.w};
    __nv_bfloat16 h0[4], h1[4], h2[4];
    #pragma unroll
    for (int i = 0; i < 4; ++i) {
        h0[i] = __float2bfloat16(a[i]);
        float r = a[i] - __bfloat162float(h0[i]);
        h1[i] = __float2bfloat16(r);
        float r2 = r - __bfloat162float(h1[i]);
        h2[i] = __float2bfloat16(r2);
    }
    *reinterpret_cast<uint2*>(d0 + o) = *reinterpret_cast<uint2*>(h0);
    *reinterpret_cast<uint2*>(d1 + o) = *reinterpret_cast<uint2*>(h1);
    *reinterpret_cast<uint2*>(d2 + o) = *reinterpret_cast<uint2*>(h2);
}

__global__ void split_kernel(const float* __restrict__ src, int which)
{
    __nv_bfloat16 *d0, *d1, *d2;
    int cols, srcld;
    switch (which) {
        case 0:  d0 = g_X0;  d1 = g_X1;  d2 = g_X2;  cols = DD; srcld = DD;   break;
        case 1:  d0 = g_P0;  d1 = g_P1;  d2 = g_P2;  cols = RB; srcld = MAXD; break;
        case 2:  d0 = g_Wi0; d1 = g_Wi1; d2 = g_Wi2; cols = DD; srcld = DD;   break;
        case 3:  d0 = g_Wr0; d1 = g_Wr1; d2 = g_Wr2; cols = RB; srcld = RB;   break;
        default: d0 = g_Wg0; d1 = g_Wg1; d2 = g_Wg2; cols = DD; srcld = DD;   break;
    }
    size_t i4 = (size_t)blockIdx.x * blockDim.x + threadIdx.x;
    size_t e = i4 * 4;
    int row = (int)(e / cols);
    int col = (int)(e % cols);
    float4 v = *reinterpret_cast<const float4*>(src + (size_t)row * srcld + col);
    split_store(v, d0, d1, d2, e);
}

// ---------------------------------------------------------------------------
// Combine + spike + pad
__global__ void combine_kernel(const float* __restrict__ P, float* __restrict__ out)
{
    size_t idx = (size_t)blockIdx.x * blockDim.x + threadIdx.x;
    if (idx >= (size_t)BB * (MAXD / 4)) return;
    int row = (int)(idx / (MAXD / 4));
    int c4  = (int)(idx % (MAXD / 4));

    float4 o4;
    if (c4 < RB / 4) {
        int c = c4 * 4;
        float4 z  = *(const float4*)(g_Z + (size_t)row * RB + c);
        float4 gi = *(const float4*)(g_G + (size_t)row * GN + c);
        float4 gf = *(const float4*)(g_G + (size_t)row * GN + RB + c);
        float4 go = *(const float4*)(g_G + (size_t)row * GN + 2 * RB + c);
        float4 p  = *(const float4*)(P   + (size_t)row * MAXD + c);

        float zz[4] = {z.x, z.y, z.z, z.w};
        float ii[4] = {gi.x, gi.y, gi.z, gi.w};
        float ff[4] = {gf.x, gf.y, gf.z, gf.w};
        float oo[4] = {go.x, go.y, go.z, go.w};
        float pp[4] = {p.x, p.y, p.z, p.w};
        float s[4];
        #pragma unroll
        for (int l = 0; l < 4; ++l) {
            float v = 0.9f * (ff[l] * pp[l]) + 0.1f * tanhf(ii[l] * zz[l]);
            v = oo[l] * v;
            if (v > 0.5f) v -= 0.5f;
            s[l] = v;
        }
        o4 = make_float4(s[0], s[1], s[2], s[3]);
    } else {
        o4 = make_float4(0.0f, 0.0f, 0.0f, 0.0f);
    }
    *(float4*)(out + (size_t)row * MAXD + c4 * 4) = o4;
}

// ---------------------------------------------------------------------------
extern "C" void kernel_launch(void* const* d_in, const int* in_sizes, int n_in,
                              void* d_out, int out_size)
{
    const float* X    = (const float*)d_in[0];
    const float* P    = (const float*)d_in[1];
    const float* Win  = (const float*)d_in[2];
    const float* Wres = (const float*)d_in[3];
    const float* Wg   = (const float*)d_in[4];
    float* out = (float*)d_out;

    static bool attr_set = false;
    if (!attr_set) {
        cudaFuncSetAttribute(gemm_fused_kernel,
                             cudaFuncAttributeMaxDynamicSharedMemorySize, SMEM_SIZE);
        attr_set = true;
    }

    split_kernel<<<(int)((size_t)BB * DD / 4 / 256), 256>>>(X,    0);
    split_kernel<<<(int)((size_t)BB * RB / 4 / 256), 256>>>(P,    1);
    split_kernel<<<(int)((size_t)RB * DD / 4 / 256), 256>>>(Win,  2);
    split_kernel<<<(int)((size_t)RB * RB / 4 / 256), 256>>>(Wres, 3);
    split_kernel<<<(int)((size_t)GN * DD / 4 / 256), 256>>>(Wg,   4);

    gemm_fused_kernel<<<2048, 256, SMEM_SIZE>>>();

    combine_kernel<<<(BB * (MAXD / 4) + 255) / 256, 256>>>(P, out);
}

// round 10
// speedup vs baseline: 3.2731x; 1.7127x over previous
#include <cuda_runtime.h>
#include <cuda_fp16.h>
#include <cstdint>
#include <math.h>

// ---------------------------------------------------------------------------
// Problem dims
#define BB   4096
#define DD   1024
#define RB   2048
#define GN   (3*RB)     // 6144
#define MAXD 2560

// ---------------------------------------------------------------------------
// Device-global scratch (fp16 2-way splits + fp32 intermediates)
__device__ __half g_X0[(size_t)BB*DD],  g_X1[(size_t)BB*DD];
__device__ __half g_P0[(size_t)BB*RB],  g_P1[(size_t)BB*RB];
__device__ __half g_Wi0[(size_t)RB*DD], g_Wi1[(size_t)RB*DD];
__device__ __half g_Wr0[(size_t)RB*RB], g_Wr1[(size_t)RB*RB];
__device__ __half g_Wg0[(size_t)GN*DD], g_Wg1[(size_t)GN*DD];
__device__ float g_Z[(size_t)BB*RB];
__device__ float g_G[(size_t)BB*GN];

// ---------------------------------------------------------------------------
// Tiling constants
#define BK          64
#define TILE_BYTES  (128 * 128)            // 128 rows x 64 fp16 cols = 16384 B
#define STAGE_BYTES (4 * TILE_BYTES)       // A0,A1,B0,B1 = 65536 B
#define NSTAGES     3
#define SMEM_SIZE   (NSTAGES * STAGE_BYTES) // 196608 B

__device__ __forceinline__ uint32_t smem_to_u32(const void* p) {
    uint32_t a;
    asm("{ .reg .u64 t; cvta.to.shared.u64 t, %1; cvt.u32.u64 %0, t; }" : "=r"(a) : "l"(p));
    return a;
}

__device__ __forceinline__ void ldsm_x4(uint32_t (&r)[4], uint32_t addr) {
    asm volatile("ldmatrix.sync.aligned.m8n8.x4.shared.b16 {%0,%1,%2,%3}, [%4];"
                 : "=r"(r[0]), "=r"(r[1]), "=r"(r[2]), "=r"(r[3]) : "r"(addr));
}

__device__ __forceinline__ void mma_f16(float (&c)[4], const uint32_t (&a)[4],
                                        const uint32_t* b) {
    asm volatile("mma.sync.aligned.m16n8k16.row.col.f32.f16.f16.f32 "
                 "{%0,%1,%2,%3}, {%4,%5,%6,%7}, {%8,%9}, {%0,%1,%2,%3};"
                 : "+f"(c[0]), "+f"(c[1]), "+f"(c[2]), "+f"(c[3])
                 : "r"(a[0]), "r"(a[1]), "r"(a[2]), "r"(a[3]), "r"(b[0]), "r"(b[1]));
}

// cp.async one 128x64 fp16 tile (gmem row stride ld elems) into SW128 smem tile.
__device__ __forceinline__ void cp_tile(uint32_t sm_tile, const __half* __restrict__ g,
                                        int ld, int tid) {
    #pragma unroll
    for (int i = 0; i < 4; ++i) {
        int c   = tid + (i << 8);          // 0..1023 16B-chunks
        int row = c >> 3;                  // 0..127
        int ch  = c & 7;                   // 0..7
        uint32_t off = (uint32_t)((row << 7) | (((ch ^ (row & 7))) << 4));
        const void* gp = g + (size_t)row * ld + (ch << 3);
        asm volatile("cp.async.cg.shared.global [%0], [%1], 16;"
                     :: "r"(sm_tile + off), "l"(gp));
    }
}
#define CP_COMMIT()  asm volatile("cp.async.commit_group;" ::: "memory")
#define CP_WAIT(n)   asm volatile("cp.async.wait_group %0;" :: "n"(n) : "memory")

// ---------------------------------------------------------------------------
// Load the 4 ldmatrix.x4 A fragments for one split tile at k16-step ks.
__device__ __forceinline__ void load_afr(uint32_t sTile, int lane, int wm, int ks,
                                         uint32_t (&afr)[4][4]) {
    int r  = wm + (((lane >> 3) & 1) << 3) + (lane & 7);
    int kc = (ks << 1) + (lane >> 4);
    #pragma unroll
    for (int mi = 0; mi < 4; ++mi) {
        int rr = r + mi * 16;
        uint32_t addr = (uint32_t)((rr << 7) | (((kc ^ (rr & 7))) << 4));
        ldsm_x4(afr[mi], sTile + addr);
    }
}

// 16 MMAs of one product into one accumulator set (warp tile 64x32).
__device__ __forceinline__ void do_product(float (&acc)[4][4][4],
                                           const uint32_t (&afr)[4][4],
                                           const uint32_t (&bfr)[2][4]) {
    #pragma unroll
    for (int mi = 0; mi < 4; ++mi)
        #pragma unroll
        for (int nj = 0; nj < 4; ++nj)
            mma_f16(acc[mi][nj], afr[mi], &bfr[nj >> 1][(nj & 1) << 1]);
}

// ---------------------------------------------------------------------------
// Compute one BK=64 window: 3 split-products, magnitude-ordered accumulation.
//   accL <- a0*b0 (dominant; one fp32 round per k16, like plain GEMM)
//   accS <- a0*b1, a1*b0 (~2^-11 scale; separate accumulator so their rounding
//           never happens at ulp(large sum)). a1*b1 (~2^-22) dropped.
__device__ __forceinline__ void compute_stage(uint32_t st, int lane, int wm, int wn,
                                              float (&accL)[4][4][4],
                                              float (&accS)[4][4][4])
{
    uint32_t sA = st;                       // A0, A1
    uint32_t sB = st + 2 * TILE_BYTES;      // B0, B1
    #pragma unroll
    for (int ks = 0; ks < 4; ++ks) {
        // B fragments for both splits
        uint32_t bfr[2][2][4];
        {
            int r  = wn + (((lane >> 4) & 1) << 3) + (lane & 7);
            int kc = (ks << 1) + ((lane >> 3) & 1);
            #pragma unroll
            for (int nj2 = 0; nj2 < 2; ++nj2) {
                int rr = r + nj2 * 16;
                uint32_t addr = (uint32_t)((rr << 7) | (((kc ^ (rr & 7))) << 4));
                #pragma unroll
                for (int s = 0; s < 2; ++s)
                    ldsm_x4(bfr[s][nj2], sB + s * TILE_BYTES + addr);
            }
        }
        // A split 0: (0,0)->L, (0,1)->S
        {
            uint32_t afr[4][4];
            load_afr(sA + 0 * TILE_BYTES, lane, wm, ks, afr);
            do_product(accL, afr, bfr[0]);
            do_product(accS, afr, bfr[1]);
        }
        // A split 1: (1,0)->S
        {
            uint32_t afr[4][4];
            load_afr(sA + 1 * TILE_BYTES, lane, wm, ks, afr);
            do_product(accS, afr, bfr[0]);
        }
    }
}

// ---------------------------------------------------------------------------
// One K-phase: accumulate A[bm:,k]*B[bn:,k]^T for nwin BK-windows.
// 3-stage cp.async pipeline, ONE __syncthreads per window.
__device__ __forceinline__ void run_phase(
    const __half* __restrict__ A0, const __half* __restrict__ A1, int lda,
    const __half* __restrict__ B0, const __half* __restrict__ B1, int ldb,
    int nwin, uint32_t sb, int tid, int lane, int wm, int wn,
    float (&accL)[4][4][4], float (&accS)[4][4][4])
{
    // Guard previous phase's in-flight smem reads before overwriting buffers.
    __syncthreads();

    // Prologue: windows 0 and 1 into stages 0, 1
    {
        cp_tile(sb + 0 * TILE_BYTES, A0, lda, tid);
        cp_tile(sb + 1 * TILE_BYTES, A1, lda, tid);
        cp_tile(sb + 2 * TILE_BYTES, B0, ldb, tid);
        cp_tile(sb + 3 * TILE_BYTES, B1, ldb, tid);
        CP_COMMIT();
    }
    if (nwin > 1) {
        uint32_t st = sb + STAGE_BYTES;
        cp_tile(st + 0 * TILE_BYTES, A0 + BK, lda, tid);
        cp_tile(st + 1 * TILE_BYTES, A1 + BK, lda, tid);
        cp_tile(st + 2 * TILE_BYTES, B0 + BK, ldb, tid);
        cp_tile(st + 3 * TILE_BYTES, B1 + BK, ldb, tid);
        CP_COMMIT();
    }

    for (int w = 0; w < nwin; ++w) {
        if (w + 1 < nwin) { CP_WAIT(1); } else { CP_WAIT(0); }
        __syncthreads();
        if (w + 2 < nwin) {
            uint32_t st = sb + ((w + 2) % NSTAGES) * STAGE_BYTES;
            size_t koff = (size_t)(w + 2) * BK;
            cp_tile(st + 0 * TILE_BYTES, A0 + koff, lda, tid);
            cp_tile(st + 1 * TILE_BYTES, A1 + koff, lda, tid);
            cp_tile(st + 2 * TILE_BYTES, B0 + koff, ldb, tid);
            cp_tile(st + 3 * TILE_BYTES, B1 + koff, ldb, tid);
            CP_COMMIT();
        }
        compute_stage(sb + (w % NSTAGES) * STAGE_BYTES, lane, wm, wn, accL, accS);
    }
}

// ---------------------------------------------------------------------------
// Fused GEMM kernel: blocks [0,512) -> Z (K=1024 then 2048), [512,2048) -> gates
__global__ __launch_bounds__(256, 1) void gemm_fused_kernel()
{
    extern __shared__ char smem[];
    uint32_t sb = smem_to_u32(smem);
    int tid  = threadIdx.x;
    int lane = tid & 31;
    int wid  = tid >> 5;
    int wm   = (wid & 1) * 64;     // warp M offset within 128
    int wn   = (wid >> 1) * 32;    // warp N offset within 128

    int bz = blockIdx.x;
    bool isZ = bz < 512;
    int bm, bn;
    if (isZ) { bm = (bz >> 4) * 128; bn = (bz & 15) * 128; }
    else     { int g = bz - 512; bm = (g / 48) * 128; bn = (g % 48) * 128; }

    float accL[4][4][4], accS[4][4][4];
    #pragma unroll
    for (int i = 0; i < 4; ++i)
        #pragma unroll
        for (int j = 0; j < 4; ++j)
            #pragma unroll
            for (int l = 0; l < 4; ++l) { accL[i][j][l] = 0.0f; accS[i][j][l] = 0.0f; }

    if (isZ) {
        run_phase(g_X0 + (size_t)bm * DD, g_X1 + (size_t)bm * DD, DD,
                  g_Wi0 + (size_t)bn * DD, g_Wi1 + (size_t)bn * DD, DD,
                  DD / BK, sb, tid, lane, wm, wn, accL, accS);
        run_phase(g_P0 + (size_t)bm * RB, g_P1 + (size_t)bm * RB, RB,
                  g_Wr0 + (size_t)bn * RB, g_Wr1 + (size_t)bn * RB, RB,
                  RB / BK, sb, tid, lane, wm, wn, accL, accS);
    } else {
        run_phase(g_X0 + (size_t)bm * DD, g_X1 + (size_t)bm * DD, DD,
                  g_Wg0 + (size_t)bn * DD, g_Wg1 + (size_t)bn * DD, DD,
                  DD / BK, sb, tid, lane, wm, wn, accL, accS);
    }

    // Epilogue: c-frag (mi,nj): c0,c1 at row t/4, cols (t%4)*2; c2,c3 at row t/4+8
    float* outp = isZ ? g_Z : g_G;
    int ldc = isZ ? RB : GN;
    int rbase = bm + wm + (lane >> 2);
    int cbase = bn + wn + ((lane & 3) << 1);
    #pragma unroll
    for (int mi = 0; mi < 4; ++mi) {
        #pragma unroll
        for (int nj = 0; nj < 4; ++nj) {
            int r0 = rbase + mi * 16;
            int c0 = cbase + nj * 8;
            float v0 = accL[mi][nj][0] + accS[mi][nj][0];
            float v1 = accL[mi][nj][1] + accS[mi][nj][1];
            float v2 = accL[mi][nj][2] + accS[mi][nj][2];
            float v3 = accL[mi][nj][3] + accS[mi][nj][3];
            if (!isZ) {
                v0 = 1.0f / (1.0f + expf(-v0));
                v1 = 1.0f / (1.0f + expf(-v1));
                v2 = 1.0f / (1.0f + expf(-v2));
                v3 = 1.0f / (1.0f + expf(-v3));
            }
            *reinterpret_cast<float2*>(outp + (size_t)r0 * ldc + c0)       = make_float2(v0, v1);
            *reinterpret_cast<float2*>(outp + (size_t)(r0 + 8) * ldc + c0) = make_float2(v2, v3);
        }
    }
}

// ---------------------------------------------------------------------------
// fp32 -> 2x fp16 split kernels (a = h0 + h1 + r, |r| <= 2^-22|a|;
// subnormal residuals are absolutely bounded by 2^-25)
__device__ __forceinline__ void split_store(const float4 v, __half* d0, __half* d1, size_t o)
{
    float a[4] = {v.x, v.y, v.z, v.w};
    __half h0[4], h1[4];
    #pragma unroll
    for (int i = 0; i < 4; ++i) {
        h0[i] = __float2half_rn(a[i]);
        float r = a[i] - __half2float(h0[i]);
        h1[i] = __float2half_rn(r);
    }
    *reinterpret_cast<uint2*>(d0 + o) = *reinterpret_cast<uint2*>(h0);
    *reinterpret_cast<uint2*>(d1 + o) = *reinterpret_cast<uint2*>(h1);
}

__global__ void split_kernel(const float* __restrict__ src, int which)
{
    __half *d0, *d1;
    int cols, srcld;
    switch (which) {
        case 0:  d0 = g_X0;  d1 = g_X1;  cols = DD; srcld = DD;   break;
        case 1:  d0 = g_P0;  d1 = g_P1;  cols = RB; srcld = MAXD; break;
        case 2:  d0 = g_Wi0; d1 = g_Wi1; cols = DD; srcld = DD;   break;
        case 3:  d0 = g_Wr0; d1 = g_Wr1; cols = RB; srcld = RB;   break;
        default: d0 = g_Wg0; d1 = g_Wg1; cols = DD; srcld = DD;   break;
    }
    size_t i4 = (size_t)blockIdx.x * blockDim.x + threadIdx.x;
    size_t e = i4 * 4;
    int row = (int)(e / cols);
    int col = (int)(e % cols);
    float4 v = *reinterpret_cast<const float4*>(src + (size_t)row * srcld + col);
    split_store(v, d0, d1, e);
}

// ---------------------------------------------------------------------------
// Combine + spike + pad
__global__ void combine_kernel(const float* __restrict__ P, float* __restrict__ out)
{
    size_t idx = (size_t)blockIdx.x * blockDim.x + threadIdx.x;
    if (idx >= (size_t)BB * (MAXD / 4)) return;
    int row = (int)(idx / (MAXD / 4));
    int c4  = (int)(idx % (MAXD / 4));

    float4 o4;
    if (c4 < RB / 4) {
        int c = c4 * 4;
        float4 z  = *(const float4*)(g_Z + (size_t)row * RB + c);
        float4 gi = *(const float4*)(g_G + (size_t)row * GN + c);
        float4 gf = *(const float4*)(g_G + (size_t)row * GN + RB + c);
        float4 go = *(const float4*)(g_G + (size_t)row * GN + 2 * RB + c);
        float4 p  = *(const float4*)(P   + (size_t)row * MAXD + c);

        float zz[4] = {z.x, z.y, z.z, z.w};
        float ii[4] = {gi.x, gi.y, gi.z, gi.w};
        float ff[4] = {gf.x, gf.y, gf.z, gf.w};
        float oo[4] = {go.x, go.y, go.z, go.w};
        float pp[4] = {p.x, p.y, p.z, p.w};
        float s[4];
        #pragma unroll
        for (int l = 0; l < 4; ++l) {
            float v = 0.9f * (ff[l] * pp[l]) + 0.1f * tanhf(ii[l] * zz[l]);
            v = oo[l] * v;
            if (v > 0.5f) v -= 0.5f;
            s[l] = v;
        }
        o4 = make_float4(s[0], s[1], s[2], s[3]);
    } else {
        o4 = make_float4(0.0f, 0.0f, 0.0f, 0.0f);
    }
    *(float4*)(out + (size_t)row * MAXD + c4 * 4) = o4;
}

// ---------------------------------------------------------------------------
extern "C" void kernel_launch(void* const* d_in, const int* in_sizes, int n_in,
                              void* d_out, int out_size)
{
    const float* X    = (const float*)d_in[0];
    const float* P    = (const float*)d_in[1];
    const float* Win  = (const float*)d_in[2];
    const float* Wres = (const float*)d_in[3];
    const float* Wg   = (const float*)d_in[4];
    float* out = (float*)d_out;

    static bool attr_set = false;
    if (!attr_set) {
        cudaFuncSetAttribute(gemm_fused_kernel,
                             cudaFuncAttributeMaxDynamicSharedMemorySize, SMEM_SIZE);
        attr_set = true;
    }

    split_kernel<<<(int)((size_t)BB * DD / 4 / 256), 256>>>(X,    0);
    split_kernel<<<(int)((size_t)BB * RB / 4 / 256), 256>>>(P,    1);
    split_kernel<<<(int)((size_t)RB * DD / 4 / 256), 256>>>(Win,  2);
    split_kernel<<<(int)((size_t)RB * RB / 4 / 256), 256>>>(Wres, 3);
    split_kernel<<<(int)((size_t)GN * DD / 4 / 256), 256>>>(Wg,   4);

    gemm_fused_kernel<<<2048, 256, SMEM_SIZE>>>();

    combine_kernel<<<(BB * (MAXD / 4) + 255) / 256, 256>>>(P, out);
}

// round 13
// speedup vs baseline: 3.5749x; 1.0922x over previous
#include <cuda_runtime.h>
#include <cuda_fp16.h>
#include <cstdint>
#include <math.h>

// ---------------------------------------------------------------------------
// Problem dims
#define BB   4096
#define DD   1024
#define RB   2048
#define GN   (3*RB)     // 6144
#define MAXD 2560

// ---------------------------------------------------------------------------
// Device-global scratch (fp16 2-way splits + fp32 intermediates)
__device__ __half g_X0[(size_t)BB*DD],  g_X1[(size_t)BB*DD];
__device__ __half g_P0[(size_t)BB*RB],  g_P1[(size_t)BB*RB];
__device__ __half g_Wi0[(size_t)RB*DD], g_Wi1[(size_t)RB*DD];
__device__ __half g_Wr0[(size_t)RB*RB], g_Wr1[(size_t)RB*RB];
__device__ __half g_Wg0[(size_t)GN*DD], g_Wg1[(size_t)GN*DD];
__device__ float g_Z[(size_t)BB*RB];
__device__ float g_G[(size_t)BB*GN];

// ---------------------------------------------------------------------------
// Tiling: CTA 128x64, BK=64, 2 stages -> 96KB smem -> 2 CTAs/SM.
#define BK           64
#define A_TILE_BYTES (128 * 128)            // 128 rows x 64 fp16 = 16384 B
#define B_TILE_BYTES (64 * 128)             // 64 rows x 64 fp16  = 8192 B
#define STAGE_BYTES  (2*A_TILE_BYTES + 2*B_TILE_BYTES)   // 49152 B
#define B_OFF        (2*A_TILE_BYTES)       // B0,B1 after A0,A1
#define NSTAGES      2
#define SMEM_SIZE    (NSTAGES * STAGE_BYTES) // 98304 B

__device__ __forceinline__ uint32_t smem_to_u32(const void* p) {
    uint32_t a;
    asm("{ .reg .u64 t; cvta.to.shared.u64 t, %1; cvt.u32.u64 %0, t; }" : "=r"(a) : "l"(p));
    return a;
}

__device__ __forceinline__ void ldsm_x4(uint32_t (&r)[4], uint32_t addr) {
    asm volatile("ldmatrix.sync.aligned.m8n8.x4.shared.b16 {%0,%1,%2,%3}, [%4];"
                 : "=r"(r[0]), "=r"(r[1]), "=r"(r[2]), "=r"(r[3]) : "r"(addr));
}

__device__ __forceinline__ void mma_f16(float (&c)[4], const uint32_t (&a)[4],
                                        const uint32_t* b) {
    asm volatile("mma.sync.aligned.m16n8k16.row.col.f32.f16.f16.f32 "
                 "{%0,%1,%2,%3}, {%4,%5,%6,%7}, {%8,%9}, {%0,%1,%2,%3};"
                 : "+f"(c[0]), "+f"(c[1]), "+f"(c[2]), "+f"(c[3])
                 : "r"(a[0]), "r"(a[1]), "r"(a[2]), "r"(a[3]), "r"(b[0]), "r"(b[1]));
}

// cp.async a (rows x 64) fp16 tile into SW128 smem (128B rows).
template<int ROWS>
__device__ __forceinline__ void cp_tile(uint32_t sm_tile, const __half* __restrict__ g,
                                        int ld, int tid) {
    constexpr int CHUNKS = ROWS * 8;       // 16B chunks
    #pragma unroll
    for (int i = 0; i < CHUNKS / 256; ++i) {
        int c   = tid + (i << 8);
        int row = c >> 3;
        int ch  = c & 7;
        uint32_t off = (uint32_t)((row << 7) | (((ch ^ (row & 7))) << 4));
        const void* gp = g + (size_t)row * ld + (ch << 3);
        asm volatile("cp.async.cg.shared.global [%0], [%1], 16;"
                     :: "r"(sm_tile + off), "l"(gp));
    }
}
#define CP_COMMIT()  asm volatile("cp.async.commit_group;" ::: "memory")
#define CP_WAIT(n)   asm volatile("cp.async.wait_group %0;" :: "n"(n) : "memory")

// ---------------------------------------------------------------------------
// Load 2 ldmatrix.x4 A fragments (32 rows) for one split tile at k16-step ks.
__device__ __forceinline__ void load_afr(uint32_t sTile, int lane, int wm, int ks,
                                         uint32_t (&afr)[2][4]) {
    int r  = wm + (((lane >> 3) & 1) << 3) + (lane & 7);
    int kc = (ks << 1) + (lane >> 4);
    #pragma unroll
    for (int mi = 0; mi < 2; ++mi) {
        int rr = r + mi * 16;
        uint32_t addr = (uint32_t)((rr << 7) | (((kc ^ (rr & 7))) << 4));
        ldsm_x4(afr[mi], sTile + addr);
    }
}

// 8 MMAs of one product into one accumulator set (warp tile 32x32).
__device__ __forceinline__ void do_product(float (&acc)[2][4][4],
                                           const uint32_t (&afr)[2][4],
                                           const uint32_t (&bfr)[2][4]) {
    #pragma unroll
    for (int mi = 0; mi < 2; ++mi)
        #pragma unroll
        for (int nj = 0; nj < 4; ++nj)
            mma_f16(acc[mi][nj], afr[mi], &bfr[nj >> 1][(nj & 1) << 1]);
}

// ---------------------------------------------------------------------------
// One BK=64 window: 3 split-products, magnitude-ordered accumulation.
//   accL <- a0*b0 ; accS <- a0*b1, a1*b0 (a1*b1 ~2^-22 dropped)
__device__ __forceinline__ void compute_stage(uint32_t st, int lane, int wm, int wn,
                                              float (&accL)[2][4][4],
                                              float (&accS)[2][4][4])
{
    uint32_t sA = st;
    uint32_t sB = st + B_OFF;
    #pragma unroll
    for (int ks = 0; ks < 4; ++ks) {
        uint32_t bfr[2][2][4];
        {
            int r  = wn + (((lane >> 4) & 1) << 3) + (lane & 7);
            int kc = (ks << 1) + ((lane >> 3) & 1);
            #pragma unroll
            for (int nj2 = 0; nj2 < 2; ++nj2) {
                int rr = r + nj2 * 16;
                uint32_t addr = (uint32_t)((rr << 7) | (((kc ^ (rr & 7))) << 4));
                #pragma unroll
                for (int s = 0; s < 2; ++s)
                    ldsm_x4(bfr[s][nj2], sB + s * B_TILE_BYTES + addr);
            }
        }
        {
            uint32_t afr[2][4];
            load_afr(sA + 0 * A_TILE_BYTES, lane, wm, ks, afr);
            do_product(accL, afr, bfr[0]);
            do_product(accS, afr, bfr[1]);
        }
        {
            uint32_t afr[2][4];
            load_afr(sA + 1 * A_TILE_BYTES, lane, wm, ks, afr);
            do_product(accS, afr, bfr[0]);
        }
    }
}

// ---------------------------------------------------------------------------
// One K-phase, 2-stage double buffer (compute w before loading w+2 into same stage).
__device__ __forceinline__ void run_phase(
    const __half* __restrict__ A0, const __half* __restrict__ A1, int lda,
    const __half* __restrict__ B0, const __half* __restrict__ B1, int ldb,
    int nwin, uint32_t sb, int tid, int lane, int wm, int wn,
    float (&accL)[2][4][4], float (&accS)[2][4][4])
{
    // Guard previous phase's smem reads before overwriting buffers.
    __syncthreads();

    // Prologue: windows 0 and 1 into stages 0, 1
    cp_tile<128>(sb + 0 * A_TILE_BYTES, A0, lda, tid);
    cp_tile<128>(sb + 1 * A_TILE_BYTES, A1, lda, tid);
    cp_tile< 64>(sb + B_OFF + 0 * B_TILE_BYTES, B0, ldb, tid);
    cp_tile< 64>(sb + B_OFF + 1 * B_TILE_BYTES, B1, ldb, tid);
    CP_COMMIT();
    if (nwin > 1) {
        uint32_t st = sb + STAGE_BYTES;
        cp_tile<128>(st + 0 * A_TILE_BYTES, A0 + BK, lda, tid);
        cp_tile<128>(st + 1 * A_TILE_BYTES, A1 + BK, lda, tid);
        cp_tile< 64>(st + B_OFF + 0 * B_TILE_BYTES, B0 + BK, ldb, tid);
        cp_tile< 64>(st + B_OFF + 1 * B_TILE_BYTES, B1 + BK, ldb, tid);
        CP_COMMIT();
    }

    for (int w = 0; w < nwin; ++w) {
        if (w + 1 < nwin) { CP_WAIT(1); } else { CP_WAIT(0); }
        __syncthreads();
        compute_stage(sb + (w & 1) * STAGE_BYTES, lane, wm, wn, accL, accS);
        __syncthreads();
        if (w + 2 < nwin) {
            uint32_t st = sb + (w & 1) * STAGE_BYTES;   // stage just freed
            size_t koff = (size_t)(w + 2) * BK;
            cp_tile<128>(st + 0 * A_TILE_BYTES, A0 + koff, lda, tid);
            cp_tile<128>(st + 1 * A_TILE_BYTES, A1 + koff, lda, tid);
            cp_tile< 64>(st + B_OFF + 0 * B_TILE_BYTES, B0 + koff, ldb, tid);
            cp_tile< 64>(st + B_OFF + 1 * B_TILE_BYTES, B1 + koff, ldb, tid);
            CP_COMMIT();
        }
    }
}

// ---------------------------------------------------------------------------
// Fused GEMM kernel. Blocks [0,1024): Z tiles (K=1024 then 2048);
// [1024,4096): gate tiles (K=1024). CTA tile 128x64.
__global__ __launch_bounds__(256, 2) void gemm_fused_kernel()
{
    extern __shared__ char smem[];
    uint32_t sb = smem_to_u32(smem);
    int tid  = threadIdx.x;
    int lane = tid & 31;
    int wid  = tid >> 5;
    int wm   = (wid >> 1) * 32;    // warp M offset within 128
    int wn   = (wid & 1) * 32;     // warp N offset within 64

    int bz = blockIdx.x;
    bool isZ = bz < 1024;
    int bm, bn;
    if (isZ) { bm = (bz >> 5) * 128; bn = (bz & 31) * 64; }
    else     { int g = bz - 1024; bm = (g / 96) * 128; bn = (g % 96) * 64; }

    float accL[2][4][4], accS[2][4][4];
    #pragma unroll
    for (int i = 0; i < 2; ++i)
        #pragma unroll
        for (int j = 0; j < 4; ++j)
            #pragma unroll
            for (int l = 0; l < 4; ++l) { accL[i][j][l] = 0.0f; accS[i][j][l] = 0.0f; }

    if (isZ) {
        run_phase(g_X0 + (size_t)bm * DD, g_X1 + (size_t)bm * DD, DD,
                  g_Wi0 + (size_t)bn * DD, g_Wi1 + (size_t)bn * DD, DD,
                  DD / BK, sb, tid, lane, wm, wn, accL, accS);
        run_phase(g_P0 + (size_t)bm * RB, g_P1 + (size_t)bm * RB, RB,
                  g_Wr0 + (size_t)bn * RB, g_Wr1 + (size_t)bn * RB, RB,
                  RB / BK, sb, tid, lane, wm, wn, accL, accS);
    } else {
        run_phase(g_X0 + (size_t)bm * DD, g_X1 + (size_t)bm * DD, DD,
                  g_Wg0 + (size_t)bn * DD, g_Wg1 + (size_t)bn * DD, DD,
                  DD / BK, sb, tid, lane, wm, wn, accL, accS);
    }

    // Epilogue
    float* outp = isZ ? g_Z : g_G;
    int ldc = isZ ? RB : GN;
    int rbase = bm + wm + (lane >> 2);
    int cbase = bn + wn + ((lane & 3) << 1);
    #pragma unroll
    for (int mi = 0; mi < 2; ++mi) {
        #pragma unroll
        for (int nj = 0; nj < 4; ++nj) {
            int r0 = rbase + mi * 16;
            int c0 = cbase + nj * 8;
            float v0 = accL[mi][nj][0] + accS[mi][nj][0];
            float v1 = accL[mi][nj][1] + accS[mi][nj][1];
            float v2 = accL[mi][nj][2] + accS[mi][nj][2];
            float v3 = accL[mi][nj][3] + accS[mi][nj][3];
            if (!isZ) {
                v0 = 1.0f / (1.0f + expf(-v0));
                v1 = 1.0f / (1.0f + expf(-v1));
                v2 = 1.0f / (1.0f + expf(-v2));
                v3 = 1.0f / (1.0f + expf(-v3));
            }
            *reinterpret_cast<float2*>(outp + (size_t)r0 * ldc + c0)       = make_float2(v0, v1);
            *reinterpret_cast<float2*>(outp + (size_t)(r0 + 8) * ldc + c0) = make_float2(v2, v3);
        }
    }
}

// ---------------------------------------------------------------------------
// Fused fp32 -> 2x fp16 split kernel: one launch covers all 5 tensors.
// Segment sizes in float4 units.
#define S_X   ((size_t)BB*DD/4)    // 1048576
#define S_P   ((size_t)BB*RB/4)    // 2097152
#define S_WI  ((size_t)RB*DD/4)    // 524288
#define S_WR  ((size_t)RB*RB/4)    // 1048576
#define S_WG  ((size_t)GN*DD/4)    // 1572864
#define S_TOT (S_X + S_P + S_WI + S_WR + S_WG)  // 6291456

__device__ __forceinline__ void split_store(const float4 v, __half* d0, __half* d1, size_t o)
{
    float a[4] = {v.x, v.y, v.z, v.w};
    __half h0[4], h1[4];
    #pragma unroll
    for (int i = 0; i < 4; ++i) {
        h0[i] = __float2half_rn(a[i]);
        float r = a[i] - __half2float(h0[i]);
        h1[i] = __float2half_rn(r);
    }
    *reinterpret_cast<uint2*>(d0 + o) = *reinterpret_cast<uint2*>(h0);
    *reinterpret_cast<uint2*>(d1 + o) = *reinterpret_cast<uint2*>(h1);
}

__global__ void split_all_kernel(const float* __restrict__ X, const float* __restrict__ P,
                                 const float* __restrict__ Wi, const float* __restrict__ Wr,
                                 const float* __restrict__ Wg)
{
    size_t i4 = (size_t)blockIdx.x * blockDim.x + threadIdx.x;
    if (i4 >= S_TOT) return;

    const float* src; __half *d0, *d1; size_t e; int cols, srcld;
    if (i4 < S_X) {
        src = X;  d0 = g_X0;  d1 = g_X1;  e = i4 * 4;            cols = DD; srcld = DD;
    } else if (i4 < S_X + S_P) {
        src = P;  d0 = g_P0;  d1 = g_P1;  e = (i4 - S_X) * 4;    cols = RB; srcld = MAXD;
    } else if (i4 < S_X + S_P + S_WI) {
        src = Wi; d0 = g_Wi0; d1 = g_Wi1; e = (i4 - S_X - S_P) * 4; cols = DD; srcld = DD;
    } else if (i4 < S_X + S_P + S_WI + S_WR) {
        src = Wr; d0 = g_Wr0; d1 = g_Wr1; e = (i4 - S_X - S_P - S_WI) * 4; cols = RB; srcld = RB;
    } else {
        src = Wg; d0 = g_Wg0; d1 = g_Wg1; e = (i4 - S_X - S_P - S_WI - S_WR) * 4; cols = DD; srcld = DD;
    }
    int row = (int)(e / cols);
    int col = (int)(e % cols);
    float4 v = *reinterpret_cast<const float4*>(src + (size_t)row * srcld + col);
    split_store(v, d0, d1, e);
}

// ---------------------------------------------------------------------------
// Combine + spike + pad
__global__ void combine_kernel(const float* __restrict__ P, float* __restrict__ out)
{
    size_t idx = (size_t)blockIdx.x * blockDim.x + threadIdx.x;
    if (idx >= (size_t)BB * (MAXD / 4)) return;
    int row = (int)(idx / (MAXD / 4));
    int c4  = (int)(idx % (MAXD / 4));

    float4 o4;
    if (c4 < RB / 4) {
        int c = c4 * 4;
        float4 z  = *(const float4*)(g_Z + (size_t)row * RB + c);
        float4 gi = *(const float4*)(g_G + (size_t)row * GN + c);
        float4 gf = *(const float4*)(g_G + (size_t)row * GN + RB + c);
        float4 go = *(const float4*)(g_G + (size_t)row * GN + 2 * RB + c);
        float4 p  = *(const float4*)(P   + (size_t)row * MAXD + c);

        float zz[4] = {z.x, z.y, z.z, z.w};
        float ii[4] = {gi.x, gi.y, gi.z, gi.w};
        float ff[4] = {gf.x, gf.y, gf.z, gf.w};
        float oo[4] = {go.x, go.y, go.z, go.w};
        float pp[4] = {p.x, p.y, p.z, p.w};
        float s[4];
        #pragma unroll
        for (int l = 0; l < 4; ++l) {
            float v = 0.9f * (ff[l] * pp[l]) + 0.1f * tanhf(ii[l] * zz[l]);
            v = oo[l] * v;
            if (v > 0.5f) v -= 0.5f;
            s[l] = v;
        }
        o4 = make_float4(s[0], s[1], s[2], s[3]);
    } else {
        o4 = make_float4(0.0f, 0.0f, 0.0f, 0.0f);
    }
    *(float4*)(out + (size_t)row * MAXD + c4 * 4) = o4;
}

// ---------------------------------------------------------------------------
extern "C" void kernel_launch(void* const* d_in, const int* in_sizes, int n_in,
                              void* d_out, int out_size)
{
    const float* X    = (const float*)d_in[0];
    const float* P    = (const float*)d_in[1];
    const float* Win  = (const float*)d_in[2];
    const float* Wres = (const float*)d_in[3];
    const float* Wg   = (const float*)d_in[4];
    float* out = (float*)d_out;

    static bool attr_set = false;
    if (!attr_set) {
        cudaFuncSetAttribute(gemm_fused_kernel,
                             cudaFuncAttributeMaxDynamicSharedMemorySize, SMEM_SIZE);
        attr_set = true;
    }

    split_all_kernel<<<(int)((S_TOT + 255) / 256), 256>>>(X, P, Win, Wres, Wg);
    gemm_fused_kernel<<<4096, 256, SMEM_SIZE>>>();
    combine_kernel<<<(BB * (MAXD / 4) + 255) / 256, 256>>>(P, out);
}